// round 4
// baseline (speedup 1.0000x reference)
#include <cuda_runtime.h>
#include <math.h>

#define NROWS   262144
#define HID     512
#define NHEADS  8
#define NG      1024
#define NHID1   256          // HIDDEN/2
#define LN_EPS  1e-5f
#define SM_EPS  1e-8f

#define BM      64
#define BK      32
#define XSS     66           // xs stride (pad)
#define HSS     260          // hs stride (pad)
// smem layout (floats):
//   union region [0, 16896):  mainloop: xs[32][66] (2112) + ws[32][256] (8192)
//                             epilogue: hs[64][260] (16640)
//   w2s  @16896 (2048), b1s @18944 (256), b2s @19200 (8), mu @19208 (64), rstd @19272 (64)
#define SMF_TOTAL 19336
#define SMEM_BYTES (SMF_TOTAL * 4)

static __device__ float g_logits[(size_t)NROWS * NHEADS];
static __device__ float g_maxv[NG * NHEADS];
static __device__ float g_denv[NG * NHEADS];
static __device__ int   g_off[NG + 1];

// ---------------------------------------------------------------------------
__global__ void k_init(float* __restrict__ ent)
{
    if (threadIdx.x == 0) *ent = 0.f;
}

// batch is sorted ascending; find segment boundaries (fills empty segments too)
__global__ void k_bounds(const int* __restrict__ batch)
{
    int i = blockIdx.x * blockDim.x + threadIdx.x;
    if (i >= NROWS) return;
    int cur  = batch[i];
    int prev = (i == 0) ? -1 : batch[i - 1];
    for (int g = prev + 1; g <= cur; ++g) g_off[g] = i;
    if (i == NROWS - 1) {
        for (int g = cur + 1; g <= NG; ++g) g_off[g] = NROWS;
    }
}

// ---------------------------------------------------------------------------
// Fused LayerNorm + GEMM1(512x256) + SiLU + GEMM2(256x8) -> logits [N,8]
__global__ __launch_bounds__(256, 2)
void k_logits(const float* __restrict__ x,
              const float* __restrict__ gamma,
              const float* __restrict__ beta,
              const float* __restrict__ W1,
              const float* __restrict__ b1,
              const float* __restrict__ W2,
              const float* __restrict__ b2)
{
    extern __shared__ float sm[];
    float* xs  = sm;                 // [32][66]  (transposed: xs[k][m])
    float* ws  = sm + 32 * XSS;      // [32][256]
    float* hs  = sm;                 // [64][260] (union with xs/ws)
    float* w2s = sm + 16896;         // [256][8]
    float* b1s = w2s + 2048;         // [256]
    float* b2s = b1s + 256;          // [8]
    float* muS = b2s + 8;            // [64]
    float* rsS = muS + 64;           // [64]

    const int tid  = threadIdx.x;
    const int lane = tid & 31;
    const int wid  = tid >> 5;
    const int m_base = blockIdx.x * BM;

    for (int i = tid; i < 2048; i += 256) w2s[i] = W2[i];
    b1s[tid] = b1[tid];
    if (tid < 8) b2s[tid] = b2[tid];

    // ---- LayerNorm stats: 4 threads per row ----
    {
        int row  = tid >> 2;
        int part = tid & 3;
        const float4* xr = reinterpret_cast<const float4*>(
            x + (size_t)(m_base + row) * HID) + part * 32;
        float s = 0.f, s2 = 0.f;
        #pragma unroll
        for (int i = 0; i < 32; ++i) {
            float4 v = __ldg(xr + i);
            s  += v.x + v.y + v.z + v.w;
            s2 += v.x * v.x + v.y * v.y + v.z * v.z + v.w * v.w;
        }
        s  += __shfl_xor_sync(0xffffffffu, s, 1);
        s  += __shfl_xor_sync(0xffffffffu, s, 2);
        s2 += __shfl_xor_sync(0xffffffffu, s2, 1);
        s2 += __shfl_xor_sync(0xffffffffu, s2, 2);
        if (part == 0) {
            float m = s * (1.f / HID);
            float v = s2 * (1.f / HID) - m * m;
            muS[row] = m;
            rsS[row] = rsqrtf(v + LN_EPS);
        }
    }
    __syncthreads();

    float acc[8][8];
    #pragma unroll
    for (int i = 0; i < 8; ++i)
        #pragma unroll
        for (int j = 0; j < 8; ++j) acc[i][j] = 0.f;

    const int m0 = wid * 8;   // warp owns rows m0..m0+7 (a-frag broadcasts)
    const int n0 = lane * 8;  // lane owns cols n0..n0+7

    for (int kc = 0; kc < HID; kc += BK) {
        // load x tile, apply LN, store transposed
        #pragma unroll
        for (int q = 0; q < 2; ++q) {
            int slot = tid * 2 + q;          // 0..511
            int row  = slot >> 3;
            int kk4  = (slot & 7) * 4;
            float4 v  = __ldg(reinterpret_cast<const float4*>(
                x + (size_t)(m_base + row) * HID + kc + kk4));
            float4 gm = __ldg(reinterpret_cast<const float4*>(gamma + kc + kk4));
            float4 bt = __ldg(reinterpret_cast<const float4*>(beta  + kc + kk4));
            float m = muS[row], rs = rsS[row];
            xs[(kk4 + 0) * XSS + row] = (v.x - m) * rs * gm.x + bt.x;
            xs[(kk4 + 1) * XSS + row] = (v.y - m) * rs * gm.y + bt.y;
            xs[(kk4 + 2) * XSS + row] = (v.z - m) * rs * gm.z + bt.z;
            xs[(kk4 + 3) * XSS + row] = (v.w - m) * rs * gm.w + bt.w;
        }
        // load W1 tile [32][256]
        #pragma unroll
        for (int q = 0; q < 8; ++q) {
            int slot = tid + q * 256;        // 0..2047
            int kr = slot >> 6;
            int nq = (slot & 63) * 4;
            float4 v = __ldg(reinterpret_cast<const float4*>(
                W1 + (size_t)(kc + kr) * NHID1 + nq));
            *reinterpret_cast<float4*>(ws + kr * NHID1 + nq) = v;
        }
        __syncthreads();

        #pragma unroll
        for (int kk = 0; kk < BK; ++kk) {
            float a[8], b[8];
            #pragma unroll
            for (int i = 0; i < 8; ++i) a[i] = xs[kk * XSS + m0 + i];
            float4 bb0 = *reinterpret_cast<const float4*>(ws + kk * NHID1 + n0);
            float4 bb1 = *reinterpret_cast<const float4*>(ws + kk * NHID1 + n0 + 4);
            b[0] = bb0.x; b[1] = bb0.y; b[2] = bb0.z; b[3] = bb0.w;
            b[4] = bb1.x; b[5] = bb1.y; b[6] = bb1.z; b[7] = bb1.w;
            #pragma unroll
            for (int i = 0; i < 8; ++i)
                #pragma unroll
                for (int j = 0; j < 8; ++j)
                    acc[i][j] += a[i] * b[j];
        }
        __syncthreads();
    }

    // ---- epilogue: bias + SiLU, stage h through smem ----
    #pragma unroll
    for (int i = 0; i < 8; ++i) {
        #pragma unroll
        for (int j = 0; j < 8; ++j) {
            float h  = acc[i][j] + b1s[n0 + j];
            float sv = h / (1.f + __expf(-h));
            hs[(m0 + i) * HSS + n0 + j] = sv;
        }
    }
    __syncthreads();

    // ---- GEMM2: logits[row][h] = sum_n h[row][n] * W2[n][h] + b2[h] ----
    {
        int row = tid >> 2;
        int h0  = (tid & 3) * 2;
        float s0 = 0.f, s1 = 0.f;
        const float* hrow = hs + row * HSS;
        #pragma unroll 8
        for (int n = 0; n < NHID1; ++n) {
            float hv = hrow[n];
            s0 += hv * w2s[n * NHEADS + h0];
            s1 += hv * w2s[n * NHEADS + h0 + 1];
        }
        size_t o = (size_t)(m_base + row) * NHEADS + h0;
        g_logits[o]     = s0 + b2s[h0];
        g_logits[o + 1] = s1 + b2s[h0 + 1];
    }
}

// ---------------------------------------------------------------------------
// per-graph segment max and sum(exp(logit - max)) per head
__global__ void k_stats()
{
    int g = blockIdx.x;
    int s = g_off[g], e = g_off[g + 1];
    int tid  = threadIdx.x;
    int lane = tid & 31;
    int wid  = tid >> 5;
    __shared__ float red[8][8];
    __shared__ float smax[8];

    float lm[8];
    #pragma unroll
    for (int h = 0; h < 8; ++h) lm[h] = -INFINITY;
    for (int r = s + tid; r < e; r += 256) {
        const float4* lp = reinterpret_cast<const float4*>(g_logits + (size_t)r * 8);
        float4 a = lp[0], b = lp[1];
        lm[0] = fmaxf(lm[0], a.x); lm[1] = fmaxf(lm[1], a.y);
        lm[2] = fmaxf(lm[2], a.z); lm[3] = fmaxf(lm[3], a.w);
        lm[4] = fmaxf(lm[4], b.x); lm[5] = fmaxf(lm[5], b.y);
        lm[6] = fmaxf(lm[6], b.z); lm[7] = fmaxf(lm[7], b.w);
    }
    #pragma unroll
    for (int h = 0; h < 8; ++h)
        #pragma unroll
        for (int o = 16; o > 0; o >>= 1)
            lm[h] = fmaxf(lm[h], __shfl_xor_sync(0xffffffffu, lm[h], o));
    if (lane == 0) {
        #pragma unroll
        for (int h = 0; h < 8; ++h) red[wid][h] = lm[h];
    }
    __syncthreads();
    if (tid < 8) {
        float m = red[0][tid];
        #pragma unroll
        for (int w = 1; w < 8; ++w) m = fmaxf(m, red[w][tid]);
        if (!(m >= -3.0e38f)) m = 0.f;   // empty segment guard (-inf -> 0)
        smax[tid] = m;
        g_maxv[g * 8 + tid] = m;
    }
    __syncthreads();

    float mx[8];
    #pragma unroll
    for (int h = 0; h < 8; ++h) mx[h] = smax[h];
    float ls[8];
    #pragma unroll
    for (int h = 0; h < 8; ++h) ls[h] = 0.f;
    for (int r = s + tid; r < e; r += 256) {
        const float4* lp = reinterpret_cast<const float4*>(g_logits + (size_t)r * 8);
        float4 a = lp[0], b = lp[1];
        ls[0] += __expf(a.x - mx[0]); ls[1] += __expf(a.y - mx[1]);
        ls[2] += __expf(a.z - mx[2]); ls[3] += __expf(a.w - mx[3]);
        ls[4] += __expf(b.x - mx[4]); ls[5] += __expf(b.y - mx[5]);
        ls[6] += __expf(b.z - mx[6]); ls[7] += __expf(b.w - mx[7]);
    }
    #pragma unroll
    for (int h = 0; h < 8; ++h)
        #pragma unroll
        for (int o = 16; o > 0; o >>= 1)
            ls[h] += __shfl_xor_sync(0xffffffffu, ls[h], o);
    if (lane == 0) {
        #pragma unroll
        for (int h = 0; h < 8; ++h) red[wid][h] = ls[h];
    }
    __syncthreads();
    if (tid < 8) {
        float d = 0.f;
        #pragma unroll
        for (int w = 0; w < 8; ++w) d += red[w][tid];
        if (!(d > 0.f)) d = 1.f;         // empty segment guard
        g_denv[g * 8 + tid] = d;
    }
}

// ---------------------------------------------------------------------------
// weights = exp(l - max) / denom; entropy accumulation
__global__ void k_weights(const int* __restrict__ batch,
                          float* __restrict__ w_out,
                          float* __restrict__ ent_out)
{
    int r = blockIdx.x * 256 + threadIdx.x;
    int b = batch[r];
    const float4* lp = reinterpret_cast<const float4*>(g_logits + (size_t)r * 8);
    const float4* mp = reinterpret_cast<const float4*>(g_maxv + b * 8);
    const float4* dp = reinterpret_cast<const float4*>(g_denv + b * 8);
    float4 l0 = lp[0], l1 = lp[1];
    float4 m0 = __ldg(mp), m1 = __ldg(mp + 1);
    float4 d0 = __ldg(dp), d1 = __ldg(dp + 1);

    float w[8];
    w[0] = __expf(l0.x - m0.x) / d0.x;
    w[1] = __expf(l0.y - m0.y) / d0.y;
    w[2] = __expf(l0.z - m0.z) / d0.z;
    w[3] = __expf(l0.w - m0.w) / d0.w;
    w[4] = __expf(l1.x - m1.x) / d1.x;
    w[5] = __expf(l1.y - m1.y) / d1.y;
    w[6] = __expf(l1.z - m1.z) / d1.z;
    w[7] = __expf(l1.w - m1.w) / d1.w;

    float4* op = reinterpret_cast<float4*>(w_out + (size_t)r * 8);
    op[0] = make_float4(w[0], w[1], w[2], w[3]);
    op[1] = make_float4(w[4], w[5], w[6], w[7]);

    float ent = 0.f;
    #pragma unroll
    for (int h = 0; h < 8; ++h) ent += w[h] * logf(w[h] + SM_EPS);
    #pragma unroll
    for (int o = 16; o > 0; o >>= 1)
        ent += __shfl_xor_sync(0xffffffffu, ent, o);
    if ((threadIdx.x & 31) == 0)
        atomicAdd(ent_out, -ent * (1.f / ((float)NG * (float)NHEADS)));
}

// ---------------------------------------------------------------------------
// graph_z[g][d] = sum_{r in seg g} x[r][d] * w[r][d/64]
__global__ void k_scatter(const float* __restrict__ x,
                          const float* __restrict__ w,
                          float* __restrict__ gz)
{
    int g = blockIdx.x;
    int d = threadIdx.x;           // 512
    int s = g_off[g], e = g_off[g + 1];
    int h = d >> 6;
    float acc = 0.f;
    int r = s;
    for (; r + 4 <= e; r += 4) {
        float x0 = __ldg(x + (size_t)(r + 0) * HID + d);
        float x1 = __ldg(x + (size_t)(r + 1) * HID + d);
        float x2 = __ldg(x + (size_t)(r + 2) * HID + d);
        float x3 = __ldg(x + (size_t)(r + 3) * HID + d);
        float w0 = __ldg(w + (size_t)(r + 0) * 8 + h);
        float w1 = __ldg(w + (size_t)(r + 1) * 8 + h);
        float w2 = __ldg(w + (size_t)(r + 2) * 8 + h);
        float w3 = __ldg(w + (size_t)(r + 3) * 8 + h);
        acc += x0 * w0 + x1 * w1 + x2 * w2 + x3 * w3;
    }
    for (; r < e; ++r)
        acc += __ldg(x + (size_t)r * HID + d) * __ldg(w + (size_t)r * 8 + h);
    gz[(size_t)g * HID + d] = acc;
}

// ---------------------------------------------------------------------------
extern "C" void kernel_launch(void* const* d_in, const int* in_sizes, int n_in,
                              void* d_out, int out_size)
{
    (void)in_sizes; (void)n_in; (void)out_size;
    const float* x     = (const float*)d_in[0];
    const int*   batch = (const int*)  d_in[1];
    const float* gamma = (const float*)d_in[2];
    const float* beta  = (const float*)d_in[3];
    const float* W1    = (const float*)d_in[4];
    const float* b1    = (const float*)d_in[5];
    const float* W2    = (const float*)d_in[6];
    const float* b2    = (const float*)d_in[7];

    float* gz    = (float*)d_out;                       // [G, 512]
    float* w_out = gz + (size_t)NG * HID;               // [N, 8]
    float* ent   = w_out + (size_t)NROWS * NHEADS;      // [1]

    cudaFuncSetAttribute(k_logits, cudaFuncAttributeMaxDynamicSharedMemorySize,
                         SMEM_BYTES);

    k_init<<<1, 32>>>(ent);
    k_bounds<<<NROWS / 256, 256>>>(batch);
    k_logits<<<NROWS / BM, 256, SMEM_BYTES>>>(x, gamma, beta, W1, b1, W2, b2);
    k_stats<<<NG, 256>>>();
    k_weights<<<NROWS / 256, 256>>>(batch, w_out, ent);
    k_scatter<<<NG, 512>>>(x, w_out, gz);
}

// round 5
// speedup vs baseline: 1.0005x; 1.0005x over previous
#include <cuda_runtime.h>
#include <math.h>

#define NROWS   262144
#define HID     512
#define NHEADS  8
#define NG      1024
#define NHID1   256          // HIDDEN/2
#define LN_EPS  1e-5f
#define SM_EPS  1e-8f

#define BM      64
#define BK      32
#define XSS     66           // xs stride (pad)
#define HSS     260          // hs stride (pad)
// smem layout (floats):
//   union region [0, 16896):  mainloop: xs[32][66] (2112) + ws[32][256] (8192)
//                             epilogue: hs[64][260] (16640)
//   w2s  @16896 (2048), b1s @18944 (256), b2s @19200 (8), mu @19208 (64), rstd @19272 (64)
#define SMF_TOTAL 19336
#define SMEM_BYTES (SMF_TOTAL * 4)

static __device__ float g_logits[(size_t)NROWS * NHEADS];
static __device__ float g_maxv[NG * NHEADS];
static __device__ float g_denv[NG * NHEADS];
static __device__ int   g_off[NG + 1];

// ---------------------------------------------------------------------------
__global__ void k_init(float* __restrict__ ent)
{
    if (threadIdx.x == 0) *ent = 0.f;
}

// batch is sorted ascending; find segment boundaries (fills empty segments too)
__global__ void k_bounds(const int* __restrict__ batch)
{
    int i = blockIdx.x * blockDim.x + threadIdx.x;
    if (i >= NROWS) return;
    int cur  = batch[i];
    int prev = (i == 0) ? -1 : batch[i - 1];
    for (int g = prev + 1; g <= cur; ++g) g_off[g] = i;
    if (i == NROWS - 1) {
        for (int g = cur + 1; g <= NG; ++g) g_off[g] = NROWS;
    }
}

// ---------------------------------------------------------------------------
// Fused LayerNorm + GEMM1(512x256) + SiLU + GEMM2(256x8) -> logits [N,8]
__global__ __launch_bounds__(256, 2)
void k_logits(const float* __restrict__ x,
              const float* __restrict__ gamma,
              const float* __restrict__ beta,
              const float* __restrict__ W1,
              const float* __restrict__ b1,
              const float* __restrict__ W2,
              const float* __restrict__ b2)
{
    extern __shared__ float sm[];
    float* xs  = sm;                 // [32][66]  (transposed: xs[k][m])
    float* ws  = sm + 32 * XSS;      // [32][256]
    float* hs  = sm;                 // [64][260] (union with xs/ws)
    float* w2s = sm + 16896;         // [256][8]
    float* b1s = w2s + 2048;         // [256]
    float* b2s = b1s + 256;          // [8]
    float* muS = b2s + 8;            // [64]
    float* rsS = muS + 64;           // [64]

    const int tid  = threadIdx.x;
    const int lane = tid & 31;
    const int wid  = tid >> 5;
    const int m_base = blockIdx.x * BM;

    for (int i = tid; i < 2048; i += 256) w2s[i] = W2[i];
    b1s[tid] = b1[tid];
    if (tid < 8) b2s[tid] = b2[tid];

    // ---- LayerNorm stats: 4 threads per row ----
    {
        int row  = tid >> 2;
        int part = tid & 3;
        const float4* xr = reinterpret_cast<const float4*>(
            x + (size_t)(m_base + row) * HID) + part * 32;
        float s = 0.f, s2 = 0.f;
        #pragma unroll
        for (int i = 0; i < 32; ++i) {
            float4 v = __ldg(xr + i);
            s  += v.x + v.y + v.z + v.w;
            s2 += v.x * v.x + v.y * v.y + v.z * v.z + v.w * v.w;
        }
        s  += __shfl_xor_sync(0xffffffffu, s, 1);
        s  += __shfl_xor_sync(0xffffffffu, s, 2);
        s2 += __shfl_xor_sync(0xffffffffu, s2, 1);
        s2 += __shfl_xor_sync(0xffffffffu, s2, 2);
        if (part == 0) {
            float m = s * (1.f / HID);
            float v = s2 * (1.f / HID) - m * m;
            muS[row] = m;
            rsS[row] = rsqrtf(v + LN_EPS);
        }
    }
    __syncthreads();

    float acc[8][8];
    #pragma unroll
    for (int i = 0; i < 8; ++i)
        #pragma unroll
        for (int j = 0; j < 8; ++j) acc[i][j] = 0.f;

    const int m0 = wid * 8;   // warp owns rows m0..m0+7 (a-frag broadcasts)
    const int n0 = lane * 8;  // lane owns cols n0..n0+7

    for (int kc = 0; kc < HID; kc += BK) {
        // load x tile, apply LN, store transposed
        #pragma unroll
        for (int q = 0; q < 2; ++q) {
            int slot = tid * 2 + q;          // 0..511
            int row  = slot >> 3;
            int kk4  = (slot & 7) * 4;
            float4 v  = __ldg(reinterpret_cast<const float4*>(
                x + (size_t)(m_base + row) * HID + kc + kk4));
            float4 gm = __ldg(reinterpret_cast<const float4*>(gamma + kc + kk4));
            float4 bt = __ldg(reinterpret_cast<const float4*>(beta  + kc + kk4));
            float m = muS[row], rs = rsS[row];
            xs[(kk4 + 0) * XSS + row] = (v.x - m) * rs * gm.x + bt.x;
            xs[(kk4 + 1) * XSS + row] = (v.y - m) * rs * gm.y + bt.y;
            xs[(kk4 + 2) * XSS + row] = (v.z - m) * rs * gm.z + bt.z;
            xs[(kk4 + 3) * XSS + row] = (v.w - m) * rs * gm.w + bt.w;
        }
        // load W1 tile [32][256]
        #pragma unroll
        for (int q = 0; q < 8; ++q) {
            int slot = tid + q * 256;        // 0..2047
            int kr = slot >> 6;
            int nq = (slot & 63) * 4;
            float4 v = __ldg(reinterpret_cast<const float4*>(
                W1 + (size_t)(kc + kr) * NHID1 + nq));
            *reinterpret_cast<float4*>(ws + kr * NHID1 + nq) = v;
        }
        __syncthreads();

        #pragma unroll
        for (int kk = 0; kk < BK; ++kk) {
            float a[8], b[8];
            #pragma unroll
            for (int i = 0; i < 8; ++i) a[i] = xs[kk * XSS + m0 + i];
            float4 bb0 = *reinterpret_cast<const float4*>(ws + kk * NHID1 + n0);
            float4 bb1 = *reinterpret_cast<const float4*>(ws + kk * NHID1 + n0 + 4);
            b[0] = bb0.x; b[1] = bb0.y; b[2] = bb0.z; b[3] = bb0.w;
            b[4] = bb1.x; b[5] = bb1.y; b[6] = bb1.z; b[7] = bb1.w;
            #pragma unroll
            for (int i = 0; i < 8; ++i)
                #pragma unroll
                for (int j = 0; j < 8; ++j)
                    acc[i][j] += a[i] * b[j];
        }
        __syncthreads();
    }

    // ---- epilogue: bias + SiLU, stage h through smem ----
    #pragma unroll
    for (int i = 0; i < 8; ++i) {
        #pragma unroll
        for (int j = 0; j < 8; ++j) {
            float h  = acc[i][j] + b1s[n0 + j];
            float sv = h / (1.f + __expf(-h));
            hs[(m0 + i) * HSS + n0 + j] = sv;
        }
    }
    __syncthreads();

    // ---- GEMM2: logits[row][h] = sum_n h[row][n] * W2[n][h] + b2[h] ----
    {
        int row = tid >> 2;
        int h0  = (tid & 3) * 2;
        float s0 = 0.f, s1 = 0.f;
        const float* hrow = hs + row * HSS;
        #pragma unroll 8
        for (int n = 0; n < NHID1; ++n) {
            float hv = hrow[n];
            s0 += hv * w2s[n * NHEADS + h0];
            s1 += hv * w2s[n * NHEADS + h0 + 1];
        }
        size_t o = (size_t)(m_base + row) * NHEADS + h0;
        g_logits[o]     = s0 + b2s[h0];
        g_logits[o + 1] = s1 + b2s[h0 + 1];
    }
}

// ---------------------------------------------------------------------------
// per-graph segment max and sum(exp(logit - max)) per head
__global__ void k_stats()
{
    int g = blockIdx.x;
    int s = g_off[g], e = g_off[g + 1];
    int tid  = threadIdx.x;
    int lane = tid & 31;
    int wid  = tid >> 5;
    __shared__ float red[8][8];
    __shared__ float smax[8];

    float lm[8];
    #pragma unroll
    for (int h = 0; h < 8; ++h) lm[h] = -INFINITY;
    for (int r = s + tid; r < e; r += 256) {
        const float4* lp = reinterpret_cast<const float4*>(g_logits + (size_t)r * 8);
        float4 a = lp[0], b = lp[1];
        lm[0] = fmaxf(lm[0], a.x); lm[1] = fmaxf(lm[1], a.y);
        lm[2] = fmaxf(lm[2], a.z); lm[3] = fmaxf(lm[3], a.w);
        lm[4] = fmaxf(lm[4], b.x); lm[5] = fmaxf(lm[5], b.y);
        lm[6] = fmaxf(lm[6], b.z); lm[7] = fmaxf(lm[7], b.w);
    }
    #pragma unroll
    for (int h = 0; h < 8; ++h)
        #pragma unroll
        for (int o = 16; o > 0; o >>= 1)
            lm[h] = fmaxf(lm[h], __shfl_xor_sync(0xffffffffu, lm[h], o));
    if (lane == 0) {
        #pragma unroll
        for (int h = 0; h < 8; ++h) red[wid][h] = lm[h];
    }
    __syncthreads();
    if (tid < 8) {
        float m = red[0][tid];
        #pragma unroll
        for (int w = 1; w < 8; ++w) m = fmaxf(m, red[w][tid]);
        if (!(m >= -3.0e38f)) m = 0.f;   // empty segment guard (-inf -> 0)
        smax[tid] = m;
        g_maxv[g * 8 + tid] = m;
    }
    __syncthreads();

    float mx[8];
    #pragma unroll
    for (int h = 0; h < 8; ++h) mx[h] = smax[h];
    float ls[8];
    #pragma unroll
    for (int h = 0; h < 8; ++h) ls[h] = 0.f;
    for (int r = s + tid; r < e; r += 256) {
        const float4* lp = reinterpret_cast<const float4*>(g_logits + (size_t)r * 8);
        float4 a = lp[0], b = lp[1];
        ls[0] += __expf(a.x - mx[0]); ls[1] += __expf(a.y - mx[1]);
        ls[2] += __expf(a.z - mx[2]); ls[3] += __expf(a.w - mx[3]);
        ls[4] += __expf(b.x - mx[4]); ls[5] += __expf(b.y - mx[5]);
        ls[6] += __expf(b.z - mx[6]); ls[7] += __expf(b.w - mx[7]);
    }
    #pragma unroll
    for (int h = 0; h < 8; ++h)
        #pragma unroll
        for (int o = 16; o > 0; o >>= 1)
            ls[h] += __shfl_xor_sync(0xffffffffu, ls[h], o);
    if (lane == 0) {
        #pragma unroll
        for (int h = 0; h < 8; ++h) red[wid][h] = ls[h];
    }
    __syncthreads();
    if (tid < 8) {
        float d = 0.f;
        #pragma unroll
        for (int w = 0; w < 8; ++w) d += red[w][tid];
        if (!(d > 0.f)) d = 1.f;         // empty segment guard
        g_denv[g * 8 + tid] = d;
    }
}

// ---------------------------------------------------------------------------
// weights = exp(l - max) / denom; entropy accumulation
__global__ void k_weights(const int* __restrict__ batch,
                          float* __restrict__ w_out,
                          float* __restrict__ ent_out)
{
    int r = blockIdx.x * 256 + threadIdx.x;
    int b = batch[r];
    const float4* lp = reinterpret_cast<const float4*>(g_logits + (size_t)r * 8);
    const float4* mp = reinterpret_cast<const float4*>(g_maxv + b * 8);
    const float4* dp = reinterpret_cast<const float4*>(g_denv + b * 8);
    float4 l0 = lp[0], l1 = lp[1];
    float4 m0 = __ldg(mp), m1 = __ldg(mp + 1);
    float4 d0 = __ldg(dp), d1 = __ldg(dp + 1);

    float w[8];
    w[0] = __expf(l0.x - m0.x) / d0.x;
    w[1] = __expf(l0.y - m0.y) / d0.y;
    w[2] = __expf(l0.z - m0.z) / d0.z;
    w[3] = __expf(l0.w - m0.w) / d0.w;
    w[4] = __expf(l1.x - m1.x) / d1.x;
    w[5] = __expf(l1.y - m1.y) / d1.y;
    w[6] = __expf(l1.z - m1.z) / d1.z;
    w[7] = __expf(l1.w - m1.w) / d1.w;

    float4* op = reinterpret_cast<float4*>(w_out + (size_t)r * 8);
    op[0] = make_float4(w[0], w[1], w[2], w[3]);
    op[1] = make_float4(w[4], w[5], w[6], w[7]);

    float ent = 0.f;
    #pragma unroll
    for (int h = 0; h < 8; ++h) ent += w[h] * logf(w[h] + SM_EPS);
    #pragma unroll
    for (int o = 16; o > 0; o >>= 1)
        ent += __shfl_xor_sync(0xffffffffu, ent, o);
    if ((threadIdx.x & 31) == 0)
        atomicAdd(ent_out, -ent * (1.f / ((float)NG * (float)NHEADS)));
}

// ---------------------------------------------------------------------------
// graph_z[g][d] = sum_{r in seg g} x[r][d] * w[r][d/64]
__global__ void k_scatter(const float* __restrict__ x,
                          const float* __restrict__ w,
                          float* __restrict__ gz)
{
    int g = blockIdx.x;
    int d = threadIdx.x;           // 512
    int s = g_off[g], e = g_off[g + 1];
    int h = d >> 6;
    float acc = 0.f;
    int r = s;
    for (; r + 4 <= e; r += 4) {
        float x0 = __ldg(x + (size_t)(r + 0) * HID + d);
        float x1 = __ldg(x + (size_t)(r + 1) * HID + d);
        float x2 = __ldg(x + (size_t)(r + 2) * HID + d);
        float x3 = __ldg(x + (size_t)(r + 3) * HID + d);
        float w0 = __ldg(w + (size_t)(r + 0) * 8 + h);
        float w1 = __ldg(w + (size_t)(r + 1) * 8 + h);
        float w2 = __ldg(w + (size_t)(r + 2) * 8 + h);
        float w3 = __ldg(w + (size_t)(r + 3) * 8 + h);
        acc += x0 * w0 + x1 * w1 + x2 * w2 + x3 * w3;
    }
    for (; r < e; ++r)
        acc += __ldg(x + (size_t)r * HID + d) * __ldg(w + (size_t)r * 8 + h);
    gz[(size_t)g * HID + d] = acc;
}

// ---------------------------------------------------------------------------
extern "C" void kernel_launch(void* const* d_in, const int* in_sizes, int n_in,
                              void* d_out, int out_size)
{
    (void)in_sizes; (void)n_in; (void)out_size;
    const float* x     = (const float*)d_in[0];
    const int*   batch = (const int*)  d_in[1];
    const float* gamma = (const float*)d_in[2];
    const float* beta  = (const float*)d_in[3];
    const float* W1    = (const float*)d_in[4];
    const float* b1    = (const float*)d_in[5];
    const float* W2    = (const float*)d_in[6];
    const float* b2    = (const float*)d_in[7];

    float* gz    = (float*)d_out;                       // [G, 512]
    float* w_out = gz + (size_t)NG * HID;               // [N, 8]
    float* ent   = w_out + (size_t)NROWS * NHEADS;      // [1]

    cudaFuncSetAttribute(k_logits, cudaFuncAttributeMaxDynamicSharedMemorySize,
                         SMEM_BYTES);

    k_init<<<1, 32>>>(ent);
    k_bounds<<<NROWS / 256, 256>>>(batch);
    k_logits<<<NROWS / BM, 256, SMEM_BYTES>>>(x, gamma, beta, W1, b1, W2, b2);
    k_stats<<<NG, 256>>>();
    k_weights<<<NROWS / 256, 256>>>(batch, w_out, ent);
    k_scatter<<<NG, 512>>>(x, w_out, gz);
}

// round 7
// speedup vs baseline: 2.0028x; 2.0018x over previous
#include <cuda_runtime.h>
#include <cuda_bf16.h>
#include <math.h>
#include <stdint.h>

#define NROWS   262144
#define HID     512
#define NHEADS  8
#define NG      1024
#define NHID1   256
#define LN_EPS  1e-5f
#define SM_EPS  1e-8f

// ---- HMMA tiling ----
#define TM      128          // rows per CTA
#define TN      256          // full N
#define BK      32           // K per chunk
#define NCH     16           // 512 / 32
#define NTHR    512          // 16 warps

// A smem row stride: 32 bf16 + 8 pad = 40 bf16 = 80 B
#define ARS     80
// B smem row stride: 256 bf16 + 8 pad = 264 bf16 = 528 B
#define BRS     528

// per-buffer byte offsets
#define OFF_AH   0
#define OFF_AL   10240        // 128*80
#define OFF_BH   20480
#define OFF_BL   37376        // +32*528
#define BUF_SZ   54272        // per stage
// tail region
#define OFF_W2   108544       // 256*8 f32 = 8192
#define OFF_B1   116736       // 256 f32 = 1024
#define OFF_MU   117760       // 128 f32 = 512
#define OFF_RS   118272       // 128 f32 = 512
#define OFF_LG   118784       // 128*8 f32 = 4096
#define OFF_GS   122880       // 512 f32 = 2048
#define OFF_BT   124928       // 512 f32 = 2048
#define SMEM_TOT 126976

static __device__ float g_logits[(size_t)NROWS * NHEADS];
static __device__ float g_maxv[NG * NHEADS];
static __device__ float g_denv[NG * NHEADS];
static __device__ int   g_off[NG + 1];
// W1 transposed + hi/lo bf16 split, row-major [512(k)][256(n)]
static __device__ __nv_bfloat16 g_Bhi[HID * NHID1];
static __device__ __nv_bfloat16 g_Blo[HID * NHID1];

// ---------------------------------------------------------------------------
__device__ __forceinline__ uint32_t smem_u32(const void* p)
{
    uint32_t a;
    asm("{ .reg .u64 t; cvta.to.shared.u64 t, %1; cvt.u32.u64 %0, t; }"
        : "=r"(a) : "l"(p));
    return a;
}

__device__ __forceinline__ void ldsm4(uint32_t* r, uint32_t addr)
{
    asm volatile("ldmatrix.sync.aligned.m8n8.x4.shared.b16 {%0,%1,%2,%3}, [%4];"
                 : "=r"(r[0]), "=r"(r[1]), "=r"(r[2]), "=r"(r[3]) : "r"(addr));
}

__device__ __forceinline__ void ldsm4t(uint32_t* r, uint32_t addr)
{
    asm volatile("ldmatrix.sync.aligned.m8n8.x4.trans.shared.b16 {%0,%1,%2,%3}, [%4];"
                 : "=r"(r[0]), "=r"(r[1]), "=r"(r[2]), "=r"(r[3]) : "r"(addr));
}

__device__ __forceinline__ void mma16816(float* d, const uint32_t* a, const uint32_t* b)
{
    asm volatile(
        "mma.sync.aligned.m16n8k16.row.col.f32.bf16.bf16.f32 "
        "{%0,%1,%2,%3}, {%4,%5,%6,%7}, {%8,%9}, {%0,%1,%2,%3};"
        : "+f"(d[0]), "+f"(d[1]), "+f"(d[2]), "+f"(d[3])
        : "r"(a[0]), "r"(a[1]), "r"(a[2]), "r"(a[3]), "r"(b[0]), "r"(b[1]));
}

__device__ __forceinline__ void cp16(uint32_t dst, const void* src)
{
    asm volatile("cp.async.cg.shared.global [%0], [%1], 16;"
                 :: "r"(dst), "l"(src) : "memory");
}
#define CP_COMMIT() asm volatile("cp.async.commit_group;" ::: "memory")
#define CP_WAIT0()  asm volatile("cp.async.wait_group 0;" ::: "memory")

__device__ __forceinline__ unsigned pk(__nv_bfloat16 a, __nv_bfloat16 b)
{
    __nv_bfloat162 t = __halves2bfloat162(a, b);
    return *reinterpret_cast<unsigned*>(&t);
}

// ---------------------------------------------------------------------------
__global__ void k_init(float* __restrict__ ent)
{
    if (threadIdx.x == 0) *ent = 0.f;
}

__global__ void k_bounds(const int* __restrict__ batch)
{
    int i = blockIdx.x * blockDim.x + threadIdx.x;
    if (i >= NROWS) return;
    int cur  = batch[i];
    int prev = (i == 0) ? -1 : batch[i - 1];
    for (int g = prev + 1; g <= cur; ++g) g_off[g] = i;
    if (i == NROWS - 1)
        for (int g = cur + 1; g <= NG; ++g) g_off[g] = NROWS;
}

// W1 [512][256] fp32 -> bf16 hi/lo split (row-major, k-major rows)
__global__ void k_prepw(const float* __restrict__ W1)
{
    int i = blockIdx.x * 256 + threadIdx.x;     // 0 .. 512*256-1
    float v = W1[i];
    __nv_bfloat16 h = __float2bfloat16(v);
    __nv_bfloat16 l = __float2bfloat16(v - __bfloat162float(h));
    g_Bhi[i] = h;
    g_Blo[i] = l;
}

// ---------------------------------------------------------------------------
// Fused LayerNorm + GEMM1 (bf16 HMMA, 3-product hi/lo split) + SiLU + GEMM2
// ---------------------------------------------------------------------------
__global__ __launch_bounds__(NTHR, 1)
void k_logits_mma(const float* __restrict__ x,
                  const float* __restrict__ gamma,
                  const float* __restrict__ beta,
                  const float* __restrict__ b1,
                  const float* __restrict__ W2,
                  const float* __restrict__ b2)
{
    extern __shared__ char smc[];
    float* smf = reinterpret_cast<float*>(smc);
    const uint32_t sb = smem_u32(smc);

    const int tid  = threadIdx.x;
    const int wid  = tid >> 5;
    const int lane = tid & 31;
    const int m_base = blockIdx.x * TM;

    // tail-region fills
    for (int i = tid; i < 2048; i += NTHR) smf[OFF_W2 / 4 + i] = W2[i];
    if (tid < 256) smf[OFF_B1 / 4 + tid] = b1[tid];
    for (int i = tid; i < HID; i += NTHR) {
        smf[OFF_GS / 4 + i] = gamma[i];
        smf[OFF_BT / 4 + i] = beta[i];
    }
    for (int i = tid; i < TM * NHEADS; i += NTHR)
        smf[OFF_LG / 4 + i] = b2[i & 7];

    // ---- LayerNorm stats: 4 threads per row ----
    {
        int row = tid >> 2, part = tid & 3;
        const float4* xr = reinterpret_cast<const float4*>(
            x + (size_t)(m_base + row) * HID) + part * 32;
        float s = 0.f, s2 = 0.f;
        #pragma unroll 8
        for (int i = 0; i < 32; ++i) {
            float4 v = __ldg(xr + i);
            s  += v.x + v.y + v.z + v.w;
            s2 += v.x * v.x + v.y * v.y + v.z * v.z + v.w * v.w;
        }
        s  += __shfl_xor_sync(0xffffffffu, s, 1);
        s  += __shfl_xor_sync(0xffffffffu, s, 2);
        s2 += __shfl_xor_sync(0xffffffffu, s2, 1);
        s2 += __shfl_xor_sync(0xffffffffu, s2, 2);
        if (!part) {
            float m = s * (1.f / HID);
            float v = s2 * (1.f / HID) - m * m;
            smf[OFF_MU / 4 + row] = m;
            smf[OFF_RS / 4 + row] = rsqrtf(v + LN_EPS);
        }
    }
    __syncthreads();

    // per-thread tile-load geometry (fixed across chunks)
    const int a_row = tid >> 3;              // slot0 row (slot = tid + q*512)
    const int a_kq  = (tid & 7) * 4;         // f32 col within chunk, slot0
    const int a_row1 = (tid + 512) >> 3;
    const int a_kq1  = ((tid + 512) & 7) * 4;
    const float mu0 = smf[OFF_MU / 4 + a_row],  rs0 = smf[OFF_RS / 4 + a_row];
    const float mu1 = smf[OFF_MU / 4 + a_row1], rs1 = smf[OFF_RS / 4 + a_row1];
    const float* xp0 = x + (size_t)(m_base + a_row)  * HID + a_kq;
    const float* xp1 = x + (size_t)(m_base + a_row1) * HID + a_kq1;

    // B copy geometry: float4 slots j = tid + q*512, j in 0..1023
    // row = j>>5 (0..31), col8 = j&31 ; global idx = (chunk*32+row)*256 + col8*8
    const int b_r0 = tid >> 5, b_c0 = (tid & 31) * 16;           // bytes within row
    const int b_r1 = (tid + 512) >> 5, b_c1 = ((tid + 512) & 31) * 16;

    // warp MMA geometry
    const int wm = (wid >> 2) * 32;
    const int wn = (wid & 3) * 64;
    const uint32_t a_lds = (uint32_t)((wm + (lane & 15)) * ARS + (lane >> 4) * 16);
    const uint32_t b_lds = (uint32_t)((lane & 15) * BRS + (wn + (lane >> 4) * 8) * 2);

    float acc[2][8][4];
    #pragma unroll
    for (int mt = 0; mt < 2; ++mt)
        #pragma unroll
        for (int nt = 0; nt < 8; ++nt)
            #pragma unroll
            for (int e = 0; e < 4; ++e) acc[mt][nt][e] = 0.f;

    float4 xr0, xr1;

    // ---- prologue: load chunk 0 ----
    {
        const __nv_bfloat16* gh = g_Bhi;            // chunk 0
        const __nv_bfloat16* gl = g_Blo;
        cp16(sb + OFF_BH + b_r0 * BRS + b_c0, (const char*)gh + b_r0 * 512 + b_c0);
        cp16(sb + OFF_BH + b_r1 * BRS + b_c1, (const char*)gh + b_r1 * 512 + b_c1);
        cp16(sb + OFF_BL + b_r0 * BRS + b_c0, (const char*)gl + b_r0 * 512 + b_c0);
        cp16(sb + OFF_BL + b_r1 * BRS + b_c1, (const char*)gl + b_r1 * 512 + b_c1);
        CP_COMMIT();
        xr0 = __ldg(reinterpret_cast<const float4*>(xp0));
        xr1 = __ldg(reinterpret_cast<const float4*>(xp1));
    }
    // transform + store A chunk 0 into buf0
    {
        const float4 gv0 = *reinterpret_cast<const float4*>(&smf[OFF_GS / 4 + a_kq]);
        const float4 bv0 = *reinterpret_cast<const float4*>(&smf[OFF_BT / 4 + a_kq]);
        float n0 = (xr0.x - mu0) * rs0 * gv0.x + bv0.x;
        float n1 = (xr0.y - mu0) * rs0 * gv0.y + bv0.y;
        float n2 = (xr0.z - mu0) * rs0 * gv0.z + bv0.z;
        float n3 = (xr0.w - mu0) * rs0 * gv0.w + bv0.w;
        __nv_bfloat16 h0 = __float2bfloat16(n0), h1 = __float2bfloat16(n1);
        __nv_bfloat16 h2 = __float2bfloat16(n2), h3 = __float2bfloat16(n3);
        *reinterpret_cast<uint2*>(smc + OFF_AH + a_row * ARS + a_kq * 2) =
            make_uint2(pk(h0, h1), pk(h2, h3));
        *reinterpret_cast<uint2*>(smc + OFF_AL + a_row * ARS + a_kq * 2) =
            make_uint2(pk(__float2bfloat16(n0 - __bfloat162float(h0)),
                          __float2bfloat16(n1 - __bfloat162float(h1))),
                       pk(__float2bfloat16(n2 - __bfloat162float(h2)),
                          __float2bfloat16(n3 - __bfloat162float(h3))));
        const float4 gv1 = *reinterpret_cast<const float4*>(&smf[OFF_GS / 4 + a_kq1]);
        const float4 bv1 = *reinterpret_cast<const float4*>(&smf[OFF_BT / 4 + a_kq1]);
        float m0 = (xr1.x - mu1) * rs1 * gv1.x + bv1.x;
        float m1 = (xr1.y - mu1) * rs1 * gv1.y + bv1.y;
        float m2 = (xr1.z - mu1) * rs1 * gv1.z + bv1.z;
        float m3 = (xr1.w - mu1) * rs1 * gv1.w + bv1.w;
        __nv_bfloat16 j0 = __float2bfloat16(m0), j1 = __float2bfloat16(m1);
        __nv_bfloat16 j2 = __float2bfloat16(m2), j3 = __float2bfloat16(m3);
        *reinterpret_cast<uint2*>(smc + OFF_AH + a_row1 * ARS + a_kq1 * 2) =
            make_uint2(pk(j0, j1), pk(j2, j3));
        *reinterpret_cast<uint2*>(smc + OFF_AL + a_row1 * ARS + a_kq1 * 2) =
            make_uint2(pk(__float2bfloat16(m0 - __bfloat162float(j0)),
                          __float2bfloat16(m1 - __bfloat162float(j1))),
                       pk(__float2bfloat16(m2 - __bfloat162float(j2)),
                          __float2bfloat16(m3 - __bfloat162float(j3))));
    }
    CP_WAIT0();
    __syncthreads();

    // ---- mainloop ----
    for (int t = 0; t < NCH; ++t) {
        const uint32_t bufc = (uint32_t)((t & 1) * BUF_SZ);
        const uint32_t bufn = (uint32_t)(((t + 1) & 1) * BUF_SZ);

        if (t < NCH - 1) {
            const char* gh = (const char*)g_Bhi + (size_t)(t + 1) * 32 * 512;
            const char* gl = (const char*)g_Blo + (size_t)(t + 1) * 32 * 512;
            cp16(sb + bufn + OFF_BH + b_r0 * BRS + b_c0, gh + b_r0 * 512 + b_c0);
            cp16(sb + bufn + OFF_BH + b_r1 * BRS + b_c1, gh + b_r1 * 512 + b_c1);
            cp16(sb + bufn + OFF_BL + b_r0 * BRS + b_c0, gl + b_r0 * 512 + b_c0);
            cp16(sb + bufn + OFF_BL + b_r1 * BRS + b_c1, gl + b_r1 * 512 + b_c1);
            CP_COMMIT();
            xr0 = __ldg(reinterpret_cast<const float4*>(xp0 + (t + 1) * BK));
            xr1 = __ldg(reinterpret_cast<const float4*>(xp1 + (t + 1) * BK));
        }

        // MMA phase on buf bufc
        #pragma unroll
        for (int ks = 0; ks < 2; ++ks) {
            uint32_t ah[2][4], al[2][4];
            #pragma unroll
            for (int mt = 0; mt < 2; ++mt) {
                uint32_t ao = sb + bufc + a_lds + (uint32_t)(mt * 16 * ARS + ks * 32);
                ldsm4(ah[mt], ao + OFF_AH);
                ldsm4(al[mt], ao + OFF_AL);
            }
            #pragma unroll
            for (int np = 0; np < 4; ++np) {
                uint32_t bh[4], bl[4];
                uint32_t bo = sb + bufc + b_lds + (uint32_t)(ks * 16 * BRS + np * 32);
                ldsm4t(bh, bo + OFF_BH);
                ldsm4t(bl, bo + OFF_BL);
                #pragma unroll
                for (int mt = 0; mt < 2; ++mt) {
                    mma16816(acc[mt][2 * np],     ah[mt], bh);
                    mma16816(acc[mt][2 * np],     ah[mt], bl);
                    mma16816(acc[mt][2 * np],     al[mt], bh);
                    mma16816(acc[mt][2 * np + 1], ah[mt], bh + 2);
                    mma16816(acc[mt][2 * np + 1], ah[mt], bl + 2);
                    mma16816(acc[mt][2 * np + 1], al[mt], bh + 2);
                }
            }
        }

        if (t < NCH - 1) {
            // transform + store A(t+1) into bufn
            const int kb = (t + 1) * BK;
            const float4 gv0 = *reinterpret_cast<const float4*>(&smf[OFF_GS / 4 + kb + a_kq]);
            const float4 bv0 = *reinterpret_cast<const float4*>(&smf[OFF_BT / 4 + kb + a_kq]);
            float n0 = (xr0.x - mu0) * rs0 * gv0.x + bv0.x;
            float n1 = (xr0.y - mu0) * rs0 * gv0.y + bv0.y;
            float n2 = (xr0.z - mu0) * rs0 * gv0.z + bv0.z;
            float n3 = (xr0.w - mu0) * rs0 * gv0.w + bv0.w;
            __nv_bfloat16 h0 = __float2bfloat16(n0), h1 = __float2bfloat16(n1);
            __nv_bfloat16 h2 = __float2bfloat16(n2), h3 = __float2bfloat16(n3);
            *reinterpret_cast<uint2*>(smc + bufn + OFF_AH + a_row * ARS + a_kq * 2) =
                make_uint2(pk(h0, h1), pk(h2, h3));
            *reinterpret_cast<uint2*>(smc + bufn + OFF_AL + a_row * ARS + a_kq * 2) =
                make_uint2(pk(__float2bfloat16(n0 - __bfloat162float(h0)),
                              __float2bfloat16(n1 - __bfloat162float(h1))),
                           pk(__float2bfloat16(n2 - __bfloat162float(h2)),
                              __float2bfloat16(n3 - __bfloat162float(h3))));
            const float4 gv1 = *reinterpret_cast<const float4*>(&smf[OFF_GS / 4 + kb + a_kq1]);
            const float4 bv1 = *reinterpret_cast<const float4*>(&smf[OFF_BT / 4 + kb + a_kq1]);
            float m0 = (xr1.x - mu1) * rs1 * gv1.x + bv1.x;
            float m1 = (xr1.y - mu1) * rs1 * gv1.y + bv1.y;
            float m2 = (xr1.z - mu1) * rs1 * gv1.z + bv1.z;
            float m3 = (xr1.w - mu1) * rs1 * gv1.w + bv1.w;
            __nv_bfloat16 j0 = __float2bfloat16(m0), j1 = __float2bfloat16(m1);
            __nv_bfloat16 j2 = __float2bfloat16(m2), j3 = __float2bfloat16(m3);
            *reinterpret_cast<uint2*>(smc + bufn + OFF_AH + a_row1 * ARS + a_kq1 * 2) =
                make_uint2(pk(j0, j1), pk(j2, j3));
            *reinterpret_cast<uint2*>(smc + bufn + OFF_AL + a_row1 * ARS + a_kq1 * 2) =
                make_uint2(pk(__float2bfloat16(m0 - __bfloat162float(j0)),
                              __float2bfloat16(m1 - __bfloat162float(j1))),
                           pk(__float2bfloat16(m2 - __bfloat162float(j2)),
                              __float2bfloat16(m3 - __bfloat162float(j3))));
            CP_WAIT0();
        }
        __syncthreads();
    }

    // ---- epilogue: SiLU + GEMM2 (h @ W2), accumulate logits in smem ----
    const int g = lane >> 2, q = lane & 3;
    float pacc[4][8];
    #pragma unroll
    for (int r = 0; r < 4; ++r)
        #pragma unroll
        for (int h = 0; h < 8; ++h) pacc[r][h] = 0.f;

    #pragma unroll
    for (int nt = 0; nt < 8; ++nt) {
        const int c0 = wn + nt * 8 + q * 2;
        const float4 w0a = *reinterpret_cast<const float4*>(&smf[OFF_W2 / 4 + c0 * 8]);
        const float4 w0b = *reinterpret_cast<const float4*>(&smf[OFF_W2 / 4 + c0 * 8 + 4]);
        const float4 w1a = *reinterpret_cast<const float4*>(&smf[OFF_W2 / 4 + (c0 + 1) * 8]);
        const float4 w1b = *reinterpret_cast<const float4*>(&smf[OFF_W2 / 4 + (c0 + 1) * 8 + 4]);
        const float b1c0 = smf[OFF_B1 / 4 + c0];
        const float b1c1 = smf[OFF_B1 / 4 + c0 + 1];
        #pragma unroll
        for (int mt = 0; mt < 2; ++mt) {
            #pragma unroll
            for (int e = 0; e < 4; ++e) {
                float hv = acc[mt][nt][e] + ((e & 1) ? b1c1 : b1c0);
                float sv = hv / (1.f + __expf(-hv));
                const int r = mt * 2 + (e >> 1);
                const float4 wa = (e & 1) ? w1a : w0a;
                const float4 wb = (e & 1) ? w1b : w0b;
                pacc[r][0] += sv * wa.x; pacc[r][1] += sv * wa.y;
                pacc[r][2] += sv * wa.z; pacc[r][3] += sv * wa.w;
                pacc[r][4] += sv * wb.x; pacc[r][5] += sv * wb.y;
                pacc[r][6] += sv * wb.z; pacc[r][7] += sv * wb.w;
            }
        }
    }
    #pragma unroll
    for (int r = 0; r < 4; ++r)
        #pragma unroll
        for (int h = 0; h < 8; ++h) {
            pacc[r][h] += __shfl_xor_sync(0xffffffffu, pacc[r][h], 1);
            pacc[r][h] += __shfl_xor_sync(0xffffffffu, pacc[r][h], 2);
        }
    if (q == 0) {
        #pragma unroll
        for (int r = 0; r < 4; ++r) {
            const int row = wm + (r >> 1) * 16 + g + (r & 1) * 8;
            #pragma unroll
            for (int h = 0; h < 8; ++h)
                atomicAdd(&smf[OFF_LG / 4 + row * 8 + h], pacc[r][h]);
        }
    }
    __syncthreads();

    if (tid < TM) {
        const float4* src = reinterpret_cast<const float4*>(&smf[OFF_LG / 4 + tid * 8]);
        float4* dst = reinterpret_cast<float4*>(g_logits + (size_t)(m_base + tid) * 8);
        dst[0] = src[0];
        dst[1] = src[1];
    }
}

// ---------------------------------------------------------------------------
__global__ void k_stats()
{
    int g = blockIdx.x;
    int s = g_off[g], e = g_off[g + 1];
    int tid = threadIdx.x, lane = tid & 31, wid = tid >> 5;
    __shared__ float red[8][8];
    __shared__ float smax[8];

    float lm[8];
    #pragma unroll
    for (int h = 0; h < 8; ++h) lm[h] = -INFINITY;
    for (int r = s + tid; r < e; r += 256) {
        const float4* lp = reinterpret_cast<const float4*>(g_logits + (size_t)r * 8);
        float4 a = lp[0], b = lp[1];
        lm[0] = fmaxf(lm[0], a.x); lm[1] = fmaxf(lm[1], a.y);
        lm[2] = fmaxf(lm[2], a.z); lm[3] = fmaxf(lm[3], a.w);
        lm[4] = fmaxf(lm[4], b.x); lm[5] = fmaxf(lm[5], b.y);
        lm[6] = fmaxf(lm[6], b.z); lm[7] = fmaxf(lm[7], b.w);
    }
    #pragma unroll
    for (int h = 0; h < 8; ++h)
        #pragma unroll
        for (int o = 16; o > 0; o >>= 1)
            lm[h] = fmaxf(lm[h], __shfl_xor_sync(0xffffffffu, lm[h], o));
    if (lane == 0)
        #pragma unroll
        for (int h = 0; h < 8; ++h) red[wid][h] = lm[h];
    __syncthreads();
    if (tid < 8) {
        float m = red[0][tid];
        #pragma unroll
        for (int w = 1; w < 8; ++w) m = fmaxf(m, red[w][tid]);
        if (!(m >= -3.0e38f)) m = 0.f;
        smax[tid] = m;
        g_maxv[g * 8 + tid] = m;
    }
    __syncthreads();

    float mx[8], ls[8];
    #pragma unroll
    for (int h = 0; h < 8; ++h) { mx[h] = smax[h]; ls[h] = 0.f; }
    for (int r = s + tid; r < e; r += 256) {
        const float4* lp = reinterpret_cast<const float4*>(g_logits + (size_t)r * 8);
        float4 a = lp[0], b = lp[1];
        ls[0] += __expf(a.x - mx[0]); ls[1] += __expf(a.y - mx[1]);
        ls[2] += __expf(a.z - mx[2]); ls[3] += __expf(a.w - mx[3]);
        ls[4] += __expf(b.x - mx[4]); ls[5] += __expf(b.y - mx[5]);
        ls[6] += __expf(b.z - mx[6]); ls[7] += __expf(b.w - mx[7]);
    }
    #pragma unroll
    for (int h = 0; h < 8; ++h)
        #pragma unroll
        for (int o = 16; o > 0; o >>= 1)
            ls[h] += __shfl_xor_sync(0xffffffffu, ls[h], o);
    if (lane == 0)
        #pragma unroll
        for (int h = 0; h < 8; ++h) red[wid][h] = ls[h];
    __syncthreads();
    if (tid < 8) {
        float d = 0.f;
        #pragma unroll
        for (int w = 0; w < 8; ++w) d += red[w][tid];
        if (!(d > 0.f)) d = 1.f;
        g_denv[g * 8 + tid] = d;
    }
}

// ---------------------------------------------------------------------------
__global__ void k_weights(const int* __restrict__ batch,
                          float* __restrict__ w_out,
                          float* __restrict__ ent_out)
{
    int r = blockIdx.x * 256 + threadIdx.x;
    int b = batch[r];
    const float4* lp = reinterpret_cast<const float4*>(g_logits + (size_t)r * 8);
    const float4* mp = reinterpret_cast<const float4*>(g_maxv + b * 8);
    const float4* dp = reinterpret_cast<const float4*>(g_denv + b * 8);
    float4 l0 = lp[0], l1 = lp[1];
    float4 m0 = __ldg(mp), m1 = __ldg(mp + 1);
    float4 d0 = __ldg(dp), d1 = __ldg(dp + 1);

    float w[8];
    w[0] = __expf(l0.x - m0.x) / d0.x;
    w[1] = __expf(l0.y - m0.y) / d0.y;
    w[2] = __expf(l0.z - m0.z) / d0.z;
    w[3] = __expf(l0.w - m0.w) / d0.w;
    w[4] = __expf(l1.x - m1.x) / d1.x;
    w[5] = __expf(l1.y - m1.y) / d1.y;
    w[6] = __expf(l1.z - m1.z) / d1.z;
    w[7] = __expf(l1.w - m1.w) / d1.w;

    float4* op = reinterpret_cast<float4*>(w_out + (size_t)r * 8);
    op[0] = make_float4(w[0], w[1], w[2], w[3]);
    op[1] = make_float4(w[4], w[5], w[6], w[7]);

    float ent = 0.f;
    #pragma unroll
    for (int h = 0; h < 8; ++h) ent += w[h] * logf(w[h] + SM_EPS);
    #pragma unroll
    for (int o = 16; o > 0; o >>= 1)
        ent += __shfl_xor_sync(0xffffffffu, ent, o);
    if ((threadIdx.x & 31) == 0)
        atomicAdd(ent_out, -ent * (1.f / ((float)NG * (float)NHEADS)));
}

// ---------------------------------------------------------------------------
__global__ void k_scatter(const float* __restrict__ x,
                          const float* __restrict__ w,
                          float* __restrict__ gz)
{
    int g = blockIdx.x;
    int d = threadIdx.x;
    int s = g_off[g], e = g_off[g + 1];
    int h = d >> 6;
    float acc = 0.f;
    int r = s;
    for (; r + 4 <= e; r += 4) {
        float x0 = __ldg(x + (size_t)(r + 0) * HID + d);
        float x1 = __ldg(x + (size_t)(r + 1) * HID + d);
        float x2 = __ldg(x + (size_t)(r + 2) * HID + d);
        float x3 = __ldg(x + (size_t)(r + 3) * HID + d);
        float w0 = __ldg(w + (size_t)(r + 0) * 8 + h);
        float w1 = __ldg(w + (size_t)(r + 1) * 8 + h);
        float w2 = __ldg(w + (size_t)(r + 2) * 8 + h);
        float w3 = __ldg(w + (size_t)(r + 3) * 8 + h);
        acc += x0 * w0 + x1 * w1 + x2 * w2 + x3 * w3;
    }
    for (; r < e; ++r)
        acc += __ldg(x + (size_t)r * HID + d) * __ldg(w + (size_t)r * 8 + h);
    gz[(size_t)g * HID + d] = acc;
}

// ---------------------------------------------------------------------------
extern "C" void kernel_launch(void* const* d_in, const int* in_sizes, int n_in,
                              void* d_out, int out_size)
{
    (void)in_sizes; (void)n_in; (void)out_size;
    const float* x     = (const float*)d_in[0];
    const int*   batch = (const int*)  d_in[1];
    const float* gamma = (const float*)d_in[2];
    const float* beta  = (const float*)d_in[3];
    const float* W1    = (const float*)d_in[4];
    const float* b1    = (const float*)d_in[5];
    const float* W2    = (const float*)d_in[6];
    const float* b2    = (const float*)d_in[7];

    float* gz    = (float*)d_out;                    // [G, 512]
    float* w_out = gz + (size_t)NG * HID;            // [N, 8]
    float* ent   = w_out + (size_t)NROWS * NHEADS;   // [1]

    cudaFuncSetAttribute(k_logits_mma, cudaFuncAttributeMaxDynamicSharedMemorySize,
                         SMEM_TOT);

    k_init<<<1, 32>>>(ent);
    k_bounds<<<NROWS / 256, 256>>>(batch);
    k_prepw<<<HID, 256>>>(W1);
    k_logits_mma<<<NROWS / TM, NTHR, SMEM_TOT>>>(x, gamma, beta, b1, W2, b2);
    k_stats<<<NG, 256>>>();
    k_weights<<<NROWS / 256, 256>>>(batch, w_out, ent);
    k_scatter<<<NG, 512>>>(x, w_out, gz);
}